// round 5
// baseline (speedup 1.0000x reference)
#include <cuda_runtime.h>

// Problem constants
#define BB 8
#define NN 5000
#define EE 40000
#define FF 64
#define FEE 16
#define FIL 96
#define BN (BB*NN)      // 40000
#define BE (BB*EE)      // 320000
#define UPD_ELEMS (BN*FIL)   // 3,840,000
#define MSG_ELEMS (BE*FIL)   // 30,720,000
#define LN_EPS 1e-3f

// Scratch (device globals: allocation-free per harness rules)
__device__ __align__(16) float g_Pa[UPD_ELEMS];   // nodes @ Wm[0:64]
__device__ __align__(16) float g_Pb[UPD_ELEMS];   // nodes @ Wm[64:128]
__device__ __align__(16) float g_agg[UPD_ELEMS];  // segment-sum of messages

__device__ __forceinline__ float warp_sum(float v) {
#pragma unroll
    for (int o = 16; o; o >>= 1) v += __shfl_xor_sync(0xffffffffu, v, o);
    return v;
}

// ---------------------------------------------------------------------------
// K0: zero aggregation buffer (float4: 960000 vecs = 3750 blocks * 256)
// ---------------------------------------------------------------------------
__global__ void zero_agg_kernel() {
    int i = blockIdx.x * 256 + threadIdx.x;
    ((float4*)g_agg)[i] = make_float4(0.f, 0.f, 0.f, 0.f);
}

// ---------------------------------------------------------------------------
// K1: Pa|Pb = nodes(40000x64) @ [Wm[0:64] | Wm[64:128]] (64x192)
// 64-row tile, 256 threads, 8x6 micro-tile. W stored k-major transposed with
// pad 36 (row stride 144B -> 16B aligned, LDS.128 at 4-phase floor).
// ---------------------------------------------------------------------------
__global__ __launch_bounds__(256) void precompute_kernel(
    const float* __restrict__ nodes, const float* __restrict__ Wm) {
    __shared__ __align__(16) float Xs[64][32];
    __shared__ __align__(16) float Wt[192][36];   // Wt[c][k]

    int tid = threadIdx.x;
    int tx = tid & 31, ty = tid >> 5;
    int row0 = blockIdx.x * 64;

    float acc[8][6];
#pragma unroll
    for (int i = 0; i < 8; i++)
#pragma unroll
        for (int j = 0; j < 6; j++) acc[i][j] = 0.0f;

    for (int t = 0; t < 2; t++) {
        __syncthreads();
        // Wt load: 6144 elems, coalesced gmem reads (consecutive c).
#pragma unroll
        for (int it = 0; it < 24; it++) {
            int idx = tid + 256 * it;
            int k = idx / 192, c = idx % 192;
            float v = (c < 96) ? Wm[(t * 32 + k) * FIL + c]
                               : Wm[(64 + t * 32 + k) * FIL + (c - 96)];
            Wt[c][k] = v;
        }
        // X tile: 64x32 floats = 512 float4, 2 per thread.
#pragma unroll
        for (int it = 0; it < 2; it++) {
            int idx = tid + 256 * it;
            int r = idx >> 3, c4 = idx & 7;
            ((float4*)&Xs[r][0])[c4] =
                ((const float4*)(nodes + (row0 + r) * FF + t * 32))[c4];
        }
        __syncthreads();
#pragma unroll
        for (int k4 = 0; k4 < 8; k4++) {
            float4 wv[6];
#pragma unroll
            for (int j = 0; j < 6; j++)
                wv[j] = *(const float4*)&Wt[tx + 32 * j][4 * k4];
#pragma unroll
            for (int i = 0; i < 8; i++) {
                float4 xv = *(const float4*)&Xs[ty + 8 * i][4 * k4]; // broadcast
#pragma unroll
                for (int j = 0; j < 6; j++) {
                    acc[i][j] += xv.x * wv[j].x;
                    acc[i][j] += xv.y * wv[j].y;
                    acc[i][j] += xv.z * wv[j].z;
                    acc[i][j] += xv.w * wv[j].w;
                }
            }
        }
    }

#pragma unroll
    for (int i = 0; i < 8; i++) {
        int row = row0 + ty + 8 * i;
#pragma unroll
        for (int j = 0; j < 6; j++) {
            int c = tx + 32 * j;
            if (c < 96) g_Pa[row * FIL + c] = acc[i][j];
            else        g_Pb[row * FIL + (c - 96)] = acc[i][j];
        }
    }
}

// ---------------------------------------------------------------------------
// K2: per-edge message = LN(relu(Pa[src] + Pb[dst] + ef@WmC + bm)).
// One warp per edge; lanes 0..23 each own 4 contiguous channels (float4),
// so the scatter-add is ONE float4 atomic per lane (24 REDG.128 lanes/edge
// instead of 96 REDG.32 lanes).
// ---------------------------------------------------------------------------
__global__ __launch_bounds__(256) void edge_kernel(
    const float* __restrict__ ef, const int* __restrict__ edges,
    const float* __restrict__ Wm, const float* __restrict__ bm,
    const float* __restrict__ gamma, const float* __restrict__ beta,
    float* __restrict__ msg_out, int write_msg) {
    __shared__ __align__(16) float4 WmC4[16 * 24];  // Wm rows 128..143, vec4
    __shared__ __align__(16) float4 s_bm4[24], s_g4[24], s_b4[24];

    int tid = threadIdx.x;
    const float4* WmC_src = (const float4*)(Wm + 128 * FIL);
    for (int i = tid; i < 16 * 24; i += 256) WmC4[i] = WmC_src[i];
    if (tid < 24) {
        s_bm4[tid] = ((const float4*)bm)[tid];
        s_g4[tid]  = ((const float4*)gamma)[tid];
        s_b4[tid]  = ((const float4*)beta)[tid];
    }
    __syncthreads();

    int warp = tid >> 5, lane = tid & 31;
    int eidx = blockIdx.x * 8 + warp;  // BE divisible by 8

    bool active = lane < 24;
    int cl = active ? lane : 0;        // clamped index: lanes 24..31 duplicate lane 0

    int b = eidx / EE;
    int2 e2 = ((const int2*)edges)[eidx];
    int src = e2.x, dst = e2.y;

    float efv = (lane < 16) ? ef[eidx * FEE + lane] : 0.0f;

    float4 a = s_bm4[cl];
#pragma unroll
    for (int k = 0; k < 16; k++) {
        float x = __shfl_sync(0xffffffffu, efv, k);
        float4 w = WmC4[k * 24 + cl];
        a.x += x * w.x; a.y += x * w.y; a.z += x * w.z; a.w += x * w.w;
    }

    int pa4 = (b * NN + src) * 24;
    int pb4 = (b * NN + dst) * 24;
    float4 pa = ((const float4*)g_Pa)[pa4 + cl];
    float4 pb = ((const float4*)g_Pb)[pb4 + cl];
    a.x += pa.x + pb.x; a.y += pa.y + pb.y;
    a.z += pa.z + pb.z; a.w += pa.w + pb.w;

    // relu
    a.x = fmaxf(a.x, 0.f); a.y = fmaxf(a.y, 0.f);
    a.z = fmaxf(a.z, 0.f); a.w = fmaxf(a.w, 0.f);

    // LayerNorm over 96 channels (lanes >=24 contribute 0)
    float s = active ? (a.x + a.y + a.z + a.w) : 0.0f;
    float mean = warp_sum(s) * (1.0f / 96.0f);
    float4 d = make_float4(a.x - mean, a.y - mean, a.z - mean, a.w - mean);
    float sq = active ? (d.x * d.x + d.y * d.y + d.z * d.z + d.w * d.w) : 0.0f;
    float var = warp_sum(sq) * (1.0f / 96.0f);
    float inv = rsqrtf(var + LN_EPS);

    float4 g = s_g4[cl], bb = s_b4[cl];
    float4 y = make_float4(d.x * inv * g.x + bb.x, d.y * inv * g.y + bb.y,
                           d.z * inv * g.z + bb.z, d.w * inv * g.w + bb.w);

    if (active) {
        if (write_msg) ((float4*)msg_out)[eidx * 24 + lane] = y;
        atomicAdd(((float4*)g_agg) + pb4 + lane, y);  // dst = edges[...,1]
    }
}

// ---------------------------------------------------------------------------
// K3: updated = LN(relu([nodes | agg](40000x160) @ Wu(160x96) + bu))
// 64-row tile, 256 threads, 8x3 micro-tile, transposed-W smem (pad 36),
// fused ReLU + LayerNorm epilogue (warp owns complete rows).
// ---------------------------------------------------------------------------
__global__ __launch_bounds__(256) void update_kernel(
    const float* __restrict__ nodes, const float* __restrict__ Wu,
    const float* __restrict__ bu, const float* __restrict__ gamma,
    const float* __restrict__ beta, float* __restrict__ out) {
    __shared__ __align__(16) float Xs[64][32];
    __shared__ __align__(16) float Wt[96][36];   // Wt[c][k]
    __shared__ float s_bu[96], s_g[96], s_b[96];

    int tid = threadIdx.x;
    int tx = tid & 31, ty = tid >> 5;
    int row0 = blockIdx.x * 64;

    if (tid < 96) { s_bu[tid] = bu[tid]; s_g[tid] = gamma[tid]; s_b[tid] = beta[tid]; }
    __syncthreads();

    float acc[8][3];
#pragma unroll
    for (int i = 0; i < 8; i++) {
        acc[i][0] = s_bu[tx];
        acc[i][1] = s_bu[tx + 32];
        acc[i][2] = s_bu[tx + 64];
    }

    for (int t = 0; t < 5; t++) {
        __syncthreads();
        // Wt load: 3072 elems, coalesced gmem reads.
#pragma unroll
        for (int it = 0; it < 12; it++) {
            int idx = tid + 256 * it;
            int k = idx / 96, c = idx % 96;
            Wt[c][k] = Wu[(t * 32 + k) * FIL + c];
        }
        // X tile: 512 float4, 2 per thread. K-cols 0..63 from nodes, 64..159 from g_agg.
#pragma unroll
        for (int it = 0; it < 2; it++) {
            int idx = tid + 256 * it;
            int r = idx >> 3, c4 = idx & 7;
            float4 v;
            if (t < 2) v = ((const float4*)(nodes + (row0 + r) * FF + t * 32))[c4];
            else       v = ((const float4*)(g_agg + (row0 + r) * FIL + (t - 2) * 32))[c4];
            ((float4*)&Xs[r][0])[c4] = v;
        }
        __syncthreads();
#pragma unroll
        for (int k4 = 0; k4 < 8; k4++) {
            float4 w0 = *(const float4*)&Wt[tx][4 * k4];
            float4 w1 = *(const float4*)&Wt[tx + 32][4 * k4];
            float4 w2 = *(const float4*)&Wt[tx + 64][4 * k4];
#pragma unroll
            for (int i = 0; i < 8; i++) {
                float4 xv = *(const float4*)&Xs[ty + 8 * i][4 * k4]; // broadcast
                acc[i][0] += xv.x * w0.x + xv.y * w0.y + xv.z * w0.z + xv.w * w0.w;
                acc[i][1] += xv.x * w1.x + xv.y * w1.y + xv.z * w1.z + xv.w * w1.w;
                acc[i][2] += xv.x * w2.x + xv.y * w2.y + xv.z * w2.z + xv.w * w2.w;
            }
        }
    }

    // Fused ReLU + LayerNorm epilogue; warp = ty owns rows {ty+8i} completely.
#pragma unroll
    for (int i = 0; i < 8; i++) {
        int row = row0 + ty + 8 * i;
        float v0 = fmaxf(acc[i][0], 0.0f);
        float v1 = fmaxf(acc[i][1], 0.0f);
        float v2 = fmaxf(acc[i][2], 0.0f);
        float mean = warp_sum(v0 + v1 + v2) * (1.0f / 96.0f);
        float d0 = v0 - mean, d1 = v1 - mean, d2 = v2 - mean;
        float var = warp_sum(d0 * d0 + d1 * d1 + d2 * d2) * (1.0f / 96.0f);
        float inv = rsqrtf(var + LN_EPS);
        int o = row * FIL;
        out[o + tx]      = d0 * inv * s_g[tx]      + s_b[tx];
        out[o + tx + 32] = d1 * inv * s_g[tx + 32] + s_b[tx + 32];
        out[o + tx + 64] = d2 * inv * s_g[tx + 64] + s_b[tx + 64];
    }
}

// ---------------------------------------------------------------------------
// Launch: zero agg -> precompute Pa/Pb -> edge msg+LN+scatter -> node update.
// ---------------------------------------------------------------------------
extern "C" void kernel_launch(void* const* d_in, const int* in_sizes, int n_in,
                              void* d_out, int out_size) {
    const float* nodes = (const float*)d_in[0];
    const float* ef    = (const float*)d_in[1];
    const int*   edges = (const int*)d_in[2];
    const float* Wm    = (const float*)d_in[3];
    const float* bm    = (const float*)d_in[4];
    const float* ln_mg = (const float*)d_in[5];
    const float* ln_mb = (const float*)d_in[6];
    const float* Wu    = (const float*)d_in[7];
    const float* bu    = (const float*)d_in[8];
    const float* ln_ug = (const float*)d_in[9];
    const float* ln_ub = (const float*)d_in[10];

    float* out = (float*)d_out;
    float* upd_out = out;                  // updated_nodes first (tuple order)
    float* msg_out = out + UPD_ELEMS;      // then messages
    int write_msg = (out_size >= (UPD_ELEMS + MSG_ELEMS)) ? 1 : 0;
    if (!write_msg) msg_out = out;         // harmless placeholder, never stored

    zero_agg_kernel<<<UPD_ELEMS / 4 / 256, 256>>>();
    precompute_kernel<<<BN / 64, 256>>>(nodes, Wm);
    edge_kernel<<<BE / 8, 256>>>(ef, edges, Wm, bm, ln_mg, ln_mb, msg_out, write_msg);
    update_kernel<<<BN / 64, 256>>>(nodes, Wu, bu, ln_ug, ln_ub, upd_out);
}